// round 1
// baseline (speedup 1.0000x reference)
#include <cuda_runtime.h>
#include <cuda_bf16.h>

#define NN 100000
#define NE 3200000
#define HID 36
#define NH 3
#define HD 12

// ---- persistent scratch (no allocations allowed) ----
__device__ float g_feat[NN * HID];   // per-layer projected features
__device__ float g_el[NN * NH];
__device__ float g_er[NN * NH];
__device__ float g_max[NN * NH];
__device__ float g_den[NN * NH];
__device__ float g_rst[NN * HID];    // accumulator: x + bias + sum(msg); becomes next layer input (pre-ELU)

__device__ __forceinline__ void atomicMaxF(float* addr, float value) {
    // standard sign-split trick: int ordering == float ordering for non-negative,
    // unsigned-min gives max for negative floats. Mixed-sign cases are correct.
    if (value >= 0.f)
        atomicMax((int*)addr, __float_as_int(value));
    else
        atomicMin((unsigned int*)addr, (unsigned int)__float_as_int(value));
}

__device__ __forceinline__ float leaky(float v) {
    return v >= 0.f ? v : 0.2f * v;
}

// ============================================================================
// Node kernel: (optionally lin0 for first layer, else ELU of prev rst),
// feat = x @ W, el/er attention dots, init rst = x + bias, init max/den.
// One thread per node; weights staged in shared memory.
// ============================================================================
template <bool FIRST>
__global__ __launch_bounds__(128)
void node_prep(const float* __restrict__ in,
               const float* __restrict__ lin0_w, const float* __restrict__ lin0_b,
               const float* __restrict__ fc_w,
               const float* __restrict__ a_l, const float* __restrict__ a_r,
               const float* __restrict__ bias, int n_nodes) {
    __shared__ float sW[HID * HID];
    __shared__ float sW0[FIRST ? HID * HID : 1];
    __shared__ float sAl[HID], sAr[HID], sB[HID];
    __shared__ float sB0[FIRST ? HID : 1];

    int tid = threadIdx.x;
    for (int i = tid; i < HID * HID; i += blockDim.x) {
        sW[i] = fc_w[i];
        if (FIRST) sW0[i] = lin0_w[i];
    }
    for (int i = tid; i < HID; i += blockDim.x) {
        sAl[i] = a_l[i];
        sAr[i] = a_r[i];
        sB[i]  = bias[i];
        if (FIRST) sB0[i] = lin0_b[i];
    }
    __syncthreads();

    int n = blockIdx.x * blockDim.x + tid;
    if (n >= n_nodes) return;

    float x[HID];
    if (FIRST) {
        float nf[HID];
#pragma unroll
        for (int k = 0; k < HID; k++) nf[k] = in[n * HID + k];
#pragma unroll
        for (int j = 0; j < HID; j++) {
            float a = sB0[j];
#pragma unroll
            for (int k = 0; k < HID; k++) a += nf[k] * sW0[k * HID + j];
            x[j] = a;
        }
    } else {
#pragma unroll
        for (int k = 0; k < HID; k++) {
            float v = g_rst[n * HID + k];
            x[k] = v > 0.f ? v : expm1f(v);   // ELU
        }
    }

    float f[HID];
#pragma unroll
    for (int j = 0; j < HID; j++) {
        float a = 0.f;
#pragma unroll
        for (int k = 0; k < HID; k++) a += x[k] * sW[k * HID + j];
        f[j] = a;
    }

#pragma unroll
    for (int j = 0; j < HID; j++) {
        g_feat[n * HID + j] = f[j];
        g_rst[n * HID + j]  = x[j] + sB[j];  // residual + bias pre-folded
    }

#pragma unroll
    for (int h = 0; h < NH; h++) {
        float el = 0.f, er = 0.f;
#pragma unroll
        for (int d = 0; d < HD; d++) {
            el += f[h * HD + d] * sAl[h * HD + d];
            er += f[h * HD + d] * sAr[h * HD + d];
        }
        g_el[n * NH + h]  = el;
        g_er[n * NH + h]  = er;
        g_max[n * NH + h] = -1e30f;
        g_den[n * NH + h] = 0.f;
    }
}

// ============================================================================
// Edge pass 1: segment max of leaky(el[src]+er[dst]) into g_max[dst]
// ============================================================================
__global__ __launch_bounds__(256)
void edge_max(const int* __restrict__ src, const int* __restrict__ dst, int ne) {
    int e = blockIdx.x * blockDim.x + threadIdx.x;
    if (e >= ne) return;
    int s = src[e], d = dst[e];
#pragma unroll
    for (int h = 0; h < NH; h++) {
        float v = leaky(__ldg(&g_el[s * NH + h]) + __ldg(&g_er[d * NH + h]));
        atomicMaxF(&g_max[d * NH + h], v);
    }
}

// ============================================================================
// Edge pass 2: denom[dst] += exp(e - max[dst])
// ============================================================================
__global__ __launch_bounds__(256)
void edge_den(const int* __restrict__ src, const int* __restrict__ dst, int ne) {
    int e = blockIdx.x * blockDim.x + threadIdx.x;
    if (e >= ne) return;
    int s = src[e], d = dst[e];
#pragma unroll
    for (int h = 0; h < NH; h++) {
        float v  = leaky(__ldg(&g_el[s * NH + h]) + __ldg(&g_er[d * NH + h]));
        float ee = __expf(v - __ldg(&g_max[d * NH + h]));
        atomicAdd(&g_den[d * NH + h], ee);
    }
}

// ============================================================================
// Edge pass 3: alpha = exp(e-max)/max(denom,1e-9); rst[dst] += alpha*feat[src]
// Vectorized red.global.add.v4.f32 (sm_90+): 9 reductions per edge.
// ============================================================================
__global__ __launch_bounds__(256)
void edge_agg(const int* __restrict__ src, const int* __restrict__ dst, int ne) {
    int e = blockIdx.x * blockDim.x + threadIdx.x;
    if (e >= ne) return;
    int s = src[e], d = dst[e];

    float alpha[NH];
#pragma unroll
    for (int h = 0; h < NH; h++) {
        float v   = leaky(__ldg(&g_el[s * NH + h]) + __ldg(&g_er[d * NH + h]));
        float ee  = __expf(v - __ldg(&g_max[d * NH + h]));
        float den = fmaxf(__ldg(&g_den[d * NH + h]), 1e-9f);
        alpha[h]  = ee / den;
    }

    const float4* fs = reinterpret_cast<const float4*>(g_feat + (size_t)s * HID);
    float* rd = g_rst + (size_t)d * HID;
#pragma unroll
    for (int c = 0; c < 9; c++) {              // 9 float4 chunks; head = c/3
        float a = alpha[c / 3];
        float4 m4 = __ldg(&fs[c]);
        m4.x *= a; m4.y *= a; m4.z *= a; m4.w *= a;
        unsigned long long p = __cvta_generic_to_global(rd + c * 4);
        asm volatile("red.global.add.v4.f32 [%0], {%1, %2, %3, %4};"
                     :: "l"(p), "f"(m4.x), "f"(m4.y), "f"(m4.z), "f"(m4.w)
                     : "memory");
    }
}

// ============================================================================
// Output kernel: out = elu(rst) @ out_w + out_b
// ============================================================================
__global__ __launch_bounds__(128)
void out_proj(const float* __restrict__ out_w, const float* __restrict__ out_b,
              float* __restrict__ out, int n_nodes) {
    __shared__ float sW[HID * HID];
    __shared__ float sB[HID];
    int tid = threadIdx.x;
    for (int i = tid; i < HID * HID; i += blockDim.x) sW[i] = out_w[i];
    for (int i = tid; i < HID; i += blockDim.x) sB[i] = out_b[i];
    __syncthreads();

    int n = blockIdx.x * blockDim.x + tid;
    if (n >= n_nodes) return;

    float x[HID];
#pragma unroll
    for (int k = 0; k < HID; k++) {
        float v = g_rst[n * HID + k];
        x[k] = v > 0.f ? v : expm1f(v);
    }
#pragma unroll
    for (int j = 0; j < HID; j++) {
        float a = sB[j];
#pragma unroll
        for (int k = 0; k < HID; k++) a += x[k] * sW[k * HID + j];
        out[n * HID + j] = a;
    }
}

// ============================================================================
extern "C" void kernel_launch(void* const* d_in, const int* in_sizes, int n_in,
                              void* d_out, int out_size) {
    const float* node_features = (const float*)d_in[0];
    const int*   src           = (const int*)  d_in[1];
    const int*   dst           = (const int*)  d_in[2];
    const float* lin0_w        = (const float*)d_in[3];
    const float* lin0_b        = (const float*)d_in[4];
    const float* fc_w          = (const float*)d_in[5];
    const float* attn_l        = (const float*)d_in[6];
    const float* attn_r        = (const float*)d_in[7];
    const float* gat_bias      = (const float*)d_in[8];
    const float* out_w         = (const float*)d_in[9];
    const float* out_b         = (const float*)d_in[10];

    int n  = in_sizes[0] / HID;
    int ne = in_sizes[1];

    int nb_n = (n + 127) / 128;
    int nb_e = (ne + 255) / 256;

    for (int l = 0; l < 3; l++) {
        if (l == 0)
            node_prep<true><<<nb_n, 128>>>(node_features, lin0_w, lin0_b,
                                           fc_w, attn_l, attn_r, gat_bias, n);
        else
            node_prep<false><<<nb_n, 128>>>(nullptr, nullptr, nullptr,
                                            fc_w + l * HID * HID,
                                            attn_l + l * HID, attn_r + l * HID,
                                            gat_bias + l * HID, n);
        edge_max<<<nb_e, 256>>>(src, dst, ne);
        edge_den<<<nb_e, 256>>>(src, dst, ne);
        edge_agg<<<nb_e, 256>>>(src, dst, ne);
    }
    out_proj<<<nb_n, 128>>>(out_w, out_b, (float*)d_out, n);
}

// round 2
// speedup vs baseline: 1.8311x; 1.8311x over previous
#include <cuda_runtime.h>
#include <cuda_bf16.h>

#define NN 100000
#define NE 3200000
#define HID 36
#define NH 3
#define HD 12

// ---- persistent scratch (no allocations allowed) ----
__device__ float g_feat[NN * HID];     // projected features per layer
__device__ float g_el4[NN * 4];        // el padded to stride 4 (1-sector gather)
__device__ float g_er[NN * NH];
__device__ float g_rst[NN * HID];      // x + bias (+ msg/den added by gather)
__device__ int   g_deg[NN];
__device__ int   g_off[NN + 1];
__device__ int   g_cursor[NN];
__device__ int   g_esrc[NE];           // CSR: src node per (dst-sorted) edge

// ============================================================================
// CSR construction: histogram -> single-block scan -> scatter
// ============================================================================
__global__ __launch_bounds__(256)
void zero_deg(int n) {
    int i = blockIdx.x * blockDim.x + threadIdx.x;
    if (i < n) g_deg[i] = 0;
}

__global__ __launch_bounds__(256)
void hist(const int* __restrict__ dst, int ne) {
    int e = blockIdx.x * blockDim.x + threadIdx.x;
    if (e < ne) atomicAdd(&g_deg[dst[e]], 1);
}

__global__ __launch_bounds__(1024)
void scan_kernel(int n) {
    __shared__ int part[1024];
    int t = threadIdx.x;
    int chunk = (n + 1023) / 1024;
    int lo = t * chunk;
    int hi = lo + chunk; if (hi > n) hi = n;
    int s = 0;
    for (int i = lo; i < hi && i >= lo; i++) s += g_deg[i];
    part[t] = s;
    __syncthreads();
    // Hillis-Steele inclusive scan
    for (int d = 1; d < 1024; d <<= 1) {
        int v = (t >= d) ? part[t - d] : 0;
        __syncthreads();
        part[t] += v;
        __syncthreads();
    }
    int run = (t == 0) ? 0 : part[t - 1];
    for (int i = lo; i < hi; i++) {
        int dg = g_deg[i];
        g_off[i] = run;
        g_cursor[i] = run;
        run += dg;
    }
    if (lo < n && hi == n) g_off[n] = run;
}

__global__ __launch_bounds__(256)
void scatter(const int* __restrict__ src, const int* __restrict__ dst, int ne) {
    int e = blockIdx.x * blockDim.x + threadIdx.x;
    if (e >= ne) return;
    int pos = atomicAdd(&g_cursor[dst[e]], 1);
    g_esrc[pos] = src[e];
}

// ============================================================================
// Node kernel: input transform (lin0 or ELU of prev layer), feat = x @ W,
// el/er attention dots, rst = x + bias (residual+bias prefolded).
// ============================================================================
template <bool FIRST>
__global__ __launch_bounds__(128)
void node_prep(const float* __restrict__ in,
               const float* __restrict__ lin0_w, const float* __restrict__ lin0_b,
               const float* __restrict__ fc_w,
               const float* __restrict__ a_l, const float* __restrict__ a_r,
               const float* __restrict__ bias, int n_nodes) {
    __shared__ float sW[HID * HID];
    __shared__ float sW0[FIRST ? HID * HID : 1];
    __shared__ float sAl[HID], sAr[HID], sB[HID];
    __shared__ float sB0[FIRST ? HID : 1];

    int tid = threadIdx.x;
    for (int i = tid; i < HID * HID; i += blockDim.x) {
        sW[i] = fc_w[i];
        if (FIRST) sW0[i] = lin0_w[i];
    }
    for (int i = tid; i < HID; i += blockDim.x) {
        sAl[i] = a_l[i];
        sAr[i] = a_r[i];
        sB[i]  = bias[i];
        if (FIRST) sB0[i] = lin0_b[i];
    }
    __syncthreads();

    int n = blockIdx.x * blockDim.x + tid;
    if (n >= n_nodes) return;

    float x[HID];
    if (FIRST) {
        float nf[HID];
#pragma unroll
        for (int k = 0; k < HID; k++) nf[k] = in[n * HID + k];
#pragma unroll
        for (int j = 0; j < HID; j++) {
            float a = sB0[j];
#pragma unroll
            for (int k = 0; k < HID; k++) a += nf[k] * sW0[k * HID + j];
            x[j] = a;
        }
    } else {
#pragma unroll
        for (int k = 0; k < HID; k++) {
            float v = g_rst[n * HID + k];
            x[k] = v > 0.f ? v : expm1f(v);   // ELU
        }
    }

    float f[HID];
#pragma unroll
    for (int j = 0; j < HID; j++) {
        float a = 0.f;
#pragma unroll
        for (int k = 0; k < HID; k++) a += x[k] * sW[k * HID + j];
        f[j] = a;
    }

#pragma unroll
    for (int j = 0; j < HID; j++) {
        g_feat[n * HID + j] = f[j];
        g_rst[n * HID + j]  = x[j] + sB[j];
    }

    float el[NH], er[NH];
#pragma unroll
    for (int h = 0; h < NH; h++) {
        float l = 0.f, r = 0.f;
#pragma unroll
        for (int d = 0; d < HD; d++) {
            l += f[h * HD + d] * sAl[h * HD + d];
            r += f[h * HD + d] * sAr[h * HD + d];
        }
        el[h] = l; er[h] = r;
    }
    float4 e4 = make_float4(el[0], el[1], el[2], 0.f);
    *reinterpret_cast<float4*>(&g_el4[n * 4]) = e4;
#pragma unroll
    for (int h = 0; h < NH; h++) g_er[n * NH + h] = er[h];
}

// ============================================================================
// Fused gather-aggregate: one warp per dst node. Single pass computes the
// softmax denominator AND the weighted message sum (unnormalized softmax:
// exp(e)/sum(exp(e)) — max-subtraction dropped, e is O(1)).
// Lane c (c<9) owns float4 chunk c of the 36-dim message; head h = c/3.
// Lanes 0..2 compute ee per head and the denominator.
// ============================================================================
__global__ __launch_bounds__(256)
void gather_agg(int n_nodes) {
    int warp = (blockIdx.x * blockDim.x + threadIdx.x) >> 5;
    int lane = threadIdx.x & 31;
    if (warp >= n_nodes) return;
    int n = warp;

    int beg = g_off[n];
    int end = g_off[n + 1];

    int h = lane / 3;   // head for chunk owner; only meaningful for lane<9
    float er_h = 0.f;
    if (lane < 3) er_h = g_er[n * NH + lane];

    float4 acc = make_float4(0.f, 0.f, 0.f, 0.f);
    float den = 0.f;

#pragma unroll 4
    for (int i = beg; i < end; i++) {
        int s = g_esrc[i];                       // uniform within warp
        float ee = 0.f;
        if (lane < 3) {
            float e = g_el4[s * 4 + lane] + er_h;
            e = e >= 0.f ? e : 0.2f * e;
            ee = __expf(e);
            den += ee;
        }
        float a = __shfl_sync(0xffffffffu, ee, h);
        if (lane < 9) {
            float4 f = *reinterpret_cast<const float4*>(&g_feat[s * HID + 4 * lane]);
            acc.x += a * f.x;
            acc.y += a * f.y;
            acc.z += a * f.z;
            acc.w += a * f.w;
        }
    }

    float dh = __shfl_sync(0xffffffffu, den, h);
    if (lane < 9) {
        float inv = 1.0f / fmaxf(dh, 1e-9f);
        float4* rp = reinterpret_cast<float4*>(&g_rst[n * HID + 4 * lane]);
        float4 r = *rp;
        r.x += acc.x * inv;
        r.y += acc.y * inv;
        r.z += acc.z * inv;
        r.w += acc.w * inv;
        *rp = r;
    }
}

// ============================================================================
// Output: out = elu(rst) @ out_w + out_b
// ============================================================================
__global__ __launch_bounds__(128)
void out_proj(const float* __restrict__ out_w, const float* __restrict__ out_b,
              float* __restrict__ out, int n_nodes) {
    __shared__ float sW[HID * HID];
    __shared__ float sB[HID];
    int tid = threadIdx.x;
    for (int i = tid; i < HID * HID; i += blockDim.x) sW[i] = out_w[i];
    for (int i = tid; i < HID; i += blockDim.x) sB[i] = out_b[i];
    __syncthreads();

    int n = blockIdx.x * blockDim.x + tid;
    if (n >= n_nodes) return;

    float x[HID];
#pragma unroll
    for (int k = 0; k < HID; k++) {
        float v = g_rst[n * HID + k];
        x[k] = v > 0.f ? v : expm1f(v);
    }
#pragma unroll
    for (int j = 0; j < HID; j++) {
        float a = sB[j];
#pragma unroll
        for (int k = 0; k < HID; k++) a += x[k] * sW[k * HID + j];
        out[n * HID + j] = a;
    }
}

// ============================================================================
extern "C" void kernel_launch(void* const* d_in, const int* in_sizes, int n_in,
                              void* d_out, int out_size) {
    const float* node_features = (const float*)d_in[0];
    const int*   src           = (const int*)  d_in[1];
    const int*   dst           = (const int*)  d_in[2];
    const float* lin0_w        = (const float*)d_in[3];
    const float* lin0_b        = (const float*)d_in[4];
    const float* fc_w          = (const float*)d_in[5];
    const float* attn_l        = (const float*)d_in[6];
    const float* attn_r        = (const float*)d_in[7];
    const float* gat_bias      = (const float*)d_in[8];
    const float* out_w         = (const float*)d_in[9];
    const float* out_b         = (const float*)d_in[10];

    int n  = in_sizes[0] / HID;
    int ne = in_sizes[1];

    int nb_n  = (n + 127) / 128;
    int nb_e  = (ne + 255) / 256;
    int nb_z  = (n + 255) / 256;
    int nb_g  = (n * 32 + 255) / 256;   // one warp per node

    // CSR build (dst-sorted edge list)
    zero_deg<<<nb_z, 256>>>(n);
    hist<<<nb_e, 256>>>(dst, ne);
    scan_kernel<<<1, 1024>>>(n);
    scatter<<<nb_e, 256>>>(src, dst, ne);

    for (int l = 0; l < 3; l++) {
        if (l == 0)
            node_prep<true><<<nb_n, 128>>>(node_features, lin0_w, lin0_b,
                                           fc_w, attn_l, attn_r, gat_bias, n);
        else
            node_prep<false><<<nb_n, 128>>>(nullptr, nullptr, nullptr,
                                            fc_w + l * HID * HID,
                                            attn_l + l * HID, attn_r + l * HID,
                                            gat_bias + l * HID, n);
        gather_agg<<<nb_g, 256>>>(n);
    }
    out_proj<<<nb_n, 128>>>(out_w, out_b, (float*)d_out, n);
}

// round 3
// speedup vs baseline: 2.9035x; 1.5856x over previous
#include <cuda_runtime.h>
#include <cuda_bf16.h>

#define NN 100000
#define NE 3200000
#define HID 36
#define NH 3
#define HD 12
#define FE 40            // packed row stride: 36 feat + 3 el + 1 pad (160B, sector aligned)
#define FULL 0xffffffffu

// ---- persistent scratch ----
__device__ float g_fe[NN * FE];     // [0..35] feat, [36..38] el
__device__ float g_er[NN * NH];
__device__ float g_rst[NN * HID];   // x + bias (+ msg added by gather)
__device__ int   g_deg[NN];
__device__ int   g_off[NN + 1];
__device__ int   g_cursor[NN];
__device__ int   g_esrc[NE];
__device__ int   g_bsum[512];
__device__ int   g_bbase[512];

// ============================================================================
// CSR construction
// ============================================================================
__global__ __launch_bounds__(256)
void zero_deg(int n) {
    int i = blockIdx.x * blockDim.x + threadIdx.x;
    if (i < n) g_deg[i] = 0;
}

__global__ __launch_bounds__(256)
void hist(const int* __restrict__ dst, int ne) {
    int e = blockIdx.x * blockDim.x + threadIdx.x;
    if (e < ne) atomicAdd(&g_deg[dst[e]], 1);
}

// pass 1: per-block sums of deg
__global__ __launch_bounds__(256)
void scan_p1(int n) {
    __shared__ int sh[256];
    int t = threadIdx.x;
    int i = blockIdx.x * 256 + t;
    sh[t] = (i < n) ? g_deg[i] : 0;
    __syncthreads();
#pragma unroll
    for (int d = 128; d > 0; d >>= 1) {
        if (t < d) sh[t] += sh[t + d];
        __syncthreads();
    }
    if (t == 0) g_bsum[blockIdx.x] = sh[0];
}

// pass 2: exclusive scan of block sums (single block)
__global__ __launch_bounds__(512)
void scan_p2(int nb) {
    __shared__ int sh[512];
    int t = threadIdx.x;
    int v = (t < nb) ? g_bsum[t] : 0;
    sh[t] = v;
    __syncthreads();
    for (int d = 1; d < 512; d <<= 1) {
        int x = (t >= d) ? sh[t - d] : 0;
        __syncthreads();
        sh[t] += x;
        __syncthreads();
    }
    if (t < nb) g_bbase[t] = sh[t] - v;
}

// pass 3: per-block exclusive scan + base -> offsets & cursors
__global__ __launch_bounds__(256)
void scan_p3(int n, int ne) {
    __shared__ int sh[256];
    int t = threadIdx.x;
    int i = blockIdx.x * 256 + t;
    int v = (i < n) ? g_deg[i] : 0;
    sh[t] = v;
    __syncthreads();
    for (int d = 1; d < 256; d <<= 1) {
        int x = (t >= d) ? sh[t - d] : 0;
        __syncthreads();
        sh[t] += x;
        __syncthreads();
    }
    if (i < n) {
        int off = g_bbase[blockIdx.x] + sh[t] - v;
        g_off[i] = off;
        g_cursor[i] = off;
    }
    if (i == 0) g_off[n] = ne;
}

__global__ __launch_bounds__(256)
void scatter(const int* __restrict__ src, const int* __restrict__ dst, int ne) {
    int e = blockIdx.x * blockDim.x + threadIdx.x;
    if (e >= ne) return;
    int pos = atomicAdd(&g_cursor[dst[e]], 1);
    g_esrc[pos] = src[e];
}

// ============================================================================
// Node kernel: input transform (lin0 or ELU of prev layer), feat = x @ W,
// el/er dots; writes packed g_fe row and rst = x + bias.
// ============================================================================
template <bool FIRST>
__global__ __launch_bounds__(128)
void node_prep(const float* __restrict__ in,
               const float* __restrict__ lin0_w, const float* __restrict__ lin0_b,
               const float* __restrict__ fc_w,
               const float* __restrict__ a_l, const float* __restrict__ a_r,
               const float* __restrict__ bias, int n_nodes) {
    __shared__ float sW[HID * HID];
    __shared__ float sW0[FIRST ? HID * HID : 1];
    __shared__ float sAl[HID], sAr[HID], sB[HID];
    __shared__ float sB0[FIRST ? HID : 1];

    int tid = threadIdx.x;
    for (int i = tid; i < HID * HID; i += blockDim.x) {
        sW[i] = fc_w[i];
        if (FIRST) sW0[i] = lin0_w[i];
    }
    for (int i = tid; i < HID; i += blockDim.x) {
        sAl[i] = a_l[i];
        sAr[i] = a_r[i];
        sB[i]  = bias[i];
        if (FIRST) sB0[i] = lin0_b[i];
    }
    __syncthreads();

    int n = blockIdx.x * blockDim.x + tid;
    if (n >= n_nodes) return;

    float x[HID];
    if (FIRST) {
        float nf[HID];
#pragma unroll
        for (int k = 0; k < HID; k++) nf[k] = in[n * HID + k];
#pragma unroll
        for (int j = 0; j < HID; j++) {
            float a = sB0[j];
#pragma unroll
            for (int k = 0; k < HID; k++) a += nf[k] * sW0[k * HID + j];
            x[j] = a;
        }
    } else {
#pragma unroll
        for (int k = 0; k < HID; k++) {
            float v = g_rst[n * HID + k];
            x[k] = v > 0.f ? v : expm1f(v);   // ELU
        }
    }

    float f[HID];
#pragma unroll
    for (int j = 0; j < HID; j++) {
        float a = 0.f;
#pragma unroll
        for (int k = 0; k < HID; k++) a += x[k] * sW[k * HID + j];
        f[j] = a;
    }

#pragma unroll
    for (int j = 0; j < HID; j++) {
        g_fe[n * FE + j] = f[j];
        g_rst[n * HID + j] = x[j] + sB[j];
    }

#pragma unroll
    for (int h = 0; h < NH; h++) {
        float l = 0.f, r = 0.f;
#pragma unroll
        for (int d = 0; d < HD; d++) {
            l += f[h * HD + d] * sAl[h * HD + d];
            r += f[h * HD + d] * sAr[h * HD + d];
        }
        g_fe[n * FE + HID + h] = l;     // el packed with feat
        g_er[n * NH + h] = r;
    }
    g_fe[n * FE + 39] = 0.f;
}

// ============================================================================
// Fused gather-aggregate: one warp per dst node, 3 edges in flight.
// lane = e*9 + c (e<3 edge slot, c<9 float4 chunk), h = c/3.
// Lanes with c<3 compute exp(leaky(el[s]+er[n])) for head c of edge slot e.
// Unnormalized softmax (max-subtraction dropped; e is O(1)).
// ============================================================================
__global__ __launch_bounds__(256)
void gather_agg(int n_nodes) {
    int warp = (blockIdx.x * blockDim.x + threadIdx.x) >> 5;
    if (warp >= n_nodes) return;
    int lane = threadIdx.x & 31;
    int n = warp;

    int e = lane / 9;        // 0..2 valid, 3 for lanes 27..31
    int c = lane % 9;
    int h = c / 3;
    bool chunkL = lane < 27;
    bool eeL = chunkL && (c < 3);

    int beg = g_off[n];
    int end = g_off[n + 1];

    float er_c = eeL ? g_er[n * NH + c] : 0.f;

    float4 acc = make_float4(0.f, 0.f, 0.f, 0.f);
    float den = 0.f;

    for (int i = beg; i < end; i += 3) {
        int idx = i + e;
        bool act = chunkL && (idx < end);
        int s = act ? __ldg(&g_esrc[idx]) : 0;

        float ee = 0.f;
        if (act && c < 3) {
            float ev = __ldg(&g_fe[s * FE + HID + c]) + er_c;
            ev = ev >= 0.f ? ev : 0.2f * ev;
            ee = __expf(ev);
            den += ee;
        }
        float a = __shfl_sync(FULL, ee, e * 9 + h);
        if (act) {
            float4 f = *reinterpret_cast<const float4*>(&g_fe[s * FE + 4 * c]);
            acc.x += a * f.x;
            acc.y += a * f.y;
            acc.z += a * f.z;
            acc.w += a * f.w;
        }
    }

    // reduce the 3 edge-slot groups down to lanes 0..8
    acc.x = acc.x + __shfl_down_sync(FULL, acc.x, 9) + __shfl_down_sync(FULL, acc.x, 18);
    acc.y = acc.y + __shfl_down_sync(FULL, acc.y, 9) + __shfl_down_sync(FULL, acc.y, 18);
    acc.z = acc.z + __shfl_down_sync(FULL, acc.z, 9) + __shfl_down_sync(FULL, acc.z, 18);
    acc.w = acc.w + __shfl_down_sync(FULL, acc.w, 9) + __shfl_down_sync(FULL, acc.w, 18);
    den   = den   + __shfl_down_sync(FULL, den,   9) + __shfl_down_sync(FULL, den,   18);

    float dh = __shfl_sync(FULL, den, h);   // lanes 0..2 now hold per-head totals
    if (lane < 9) {
        float inv = 1.0f / fmaxf(dh, 1e-9f);
        float4* rp = reinterpret_cast<float4*>(&g_rst[n * HID + 4 * lane]);
        float4 r = *rp;
        r.x += acc.x * inv;
        r.y += acc.y * inv;
        r.z += acc.z * inv;
        r.w += acc.w * inv;
        *rp = r;
    }
}

// ============================================================================
// Output: out = elu(rst) @ out_w + out_b
// ============================================================================
__global__ __launch_bounds__(128)
void out_proj(const float* __restrict__ out_w, const float* __restrict__ out_b,
              float* __restrict__ out, int n_nodes) {
    __shared__ float sW[HID * HID];
    __shared__ float sB[HID];
    int tid = threadIdx.x;
    for (int i = tid; i < HID * HID; i += blockDim.x) sW[i] = out_w[i];
    for (int i = tid; i < HID; i += blockDim.x) sB[i] = out_b[i];
    __syncthreads();

    int n = blockIdx.x * blockDim.x + tid;
    if (n >= n_nodes) return;

    float x[HID];
#pragma unroll
    for (int k = 0; k < HID; k++) {
        float v = g_rst[n * HID + k];
        x[k] = v > 0.f ? v : expm1f(v);
    }
#pragma unroll
    for (int j = 0; j < HID; j++) {
        float a = sB[j];
#pragma unroll
        for (int k = 0; k < HID; k++) a += x[k] * sW[k * HID + j];
        out[n * HID + j] = a;
    }
}

// ============================================================================
extern "C" void kernel_launch(void* const* d_in, const int* in_sizes, int n_in,
                              void* d_out, int out_size) {
    const float* node_features = (const float*)d_in[0];
    const int*   src           = (const int*)  d_in[1];
    const int*   dst           = (const int*)  d_in[2];
    const float* lin0_w        = (const float*)d_in[3];
    const float* lin0_b        = (const float*)d_in[4];
    const float* fc_w          = (const float*)d_in[5];
    const float* attn_l        = (const float*)d_in[6];
    const float* attn_r        = (const float*)d_in[7];
    const float* gat_bias      = (const float*)d_in[8];
    const float* out_w         = (const float*)d_in[9];
    const float* out_b         = (const float*)d_in[10];

    int n  = in_sizes[0] / HID;
    int ne = in_sizes[1];

    int nb_n = (n + 127) / 128;
    int nb_e = (ne + 255) / 256;
    int nb_z = (n + 255) / 256;       // also the scan block count (256 nodes/block)
    int nb_g = (n * 32 + 255) / 256;  // one warp per node

    // CSR build
    zero_deg<<<nb_z, 256>>>(n);
    hist<<<nb_e, 256>>>(dst, ne);
    scan_p1<<<nb_z, 256>>>(n);
    scan_p2<<<1, 512>>>(nb_z);
    scan_p3<<<nb_z, 256>>>(n, ne);
    scatter<<<nb_e, 256>>>(src, dst, ne);

    for (int l = 0; l < 3; l++) {
        if (l == 0)
            node_prep<true><<<nb_n, 128>>>(node_features, lin0_w, lin0_b,
                                           fc_w, attn_l, attn_r, gat_bias, n);
        else
            node_prep<false><<<nb_n, 128>>>(nullptr, nullptr, nullptr,
                                            fc_w + l * HID * HID,
                                            attn_l + l * HID, attn_r + l * HID,
                                            gat_bias + l * HID, n);
        gather_agg<<<nb_g, 256>>>(n);
    }
    out_proj<<<nb_n, 128>>>(out_w, out_b, (float*)d_out, n);
}

// round 4
// speedup vs baseline: 3.1783x; 1.0946x over previous
#include <cuda_runtime.h>
#include <cuda_bf16.h>

#define NN 100000
#define NE 3200000
#define HID 36
#define NH 3
#define HD 12
#define FE 40            // packed row stride: 36 feat + 3 el + 1 pad (160B, sector aligned)
#define FULL 0xffffffffu

// ---- persistent scratch ----
__device__ float g_fe[NN * FE];     // [0..35] feat, [36..38] el
__device__ float g_er[NN * NH];
__device__ float g_rst[NN * HID];   // x + bias (+ msg added by gather)
__device__ int   g_deg[NN];
__device__ int   g_off[NN + 1];
__device__ int   g_cursor[NN];
__device__ int   g_esrc[NE];
__device__ int   g_bsum[512];
__device__ int   g_bbase[512];

// ============================================================================
// CSR construction
// ============================================================================
__global__ __launch_bounds__(256)
void zero_deg(int n) {
    int i = blockIdx.x * blockDim.x + threadIdx.x;
    if (i < n) g_deg[i] = 0;
}

// grid-stride, 4 edges per iteration per thread (MLP=4 on the atomic chain)
__global__ __launch_bounds__(256)
void hist(const int* __restrict__ dst, int ne) {
    int tid = blockIdx.x * blockDim.x + threadIdx.x;
    int stride = gridDim.x * blockDim.x;
    int nv = ne >> 2;
    const int4* d4 = reinterpret_cast<const int4*>(dst);
    for (int i = tid; i < nv; i += stride) {
        int4 d = __ldg(&d4[i]);
        atomicAdd(&g_deg[d.x], 1);
        atomicAdd(&g_deg[d.y], 1);
        atomicAdd(&g_deg[d.z], 1);
        atomicAdd(&g_deg[d.w], 1);
    }
    for (int i = (nv << 2) + tid; i < ne; i += stride)
        atomicAdd(&g_deg[dst[i]], 1);
}

// pass 1: per-block sums of deg
__global__ __launch_bounds__(256)
void scan_p1(int n) {
    __shared__ int sh[256];
    int t = threadIdx.x;
    int i = blockIdx.x * 256 + t;
    sh[t] = (i < n) ? g_deg[i] : 0;
    __syncthreads();
#pragma unroll
    for (int d = 128; d > 0; d >>= 1) {
        if (t < d) sh[t] += sh[t + d];
        __syncthreads();
    }
    if (t == 0) g_bsum[blockIdx.x] = sh[0];
}

// pass 2: exclusive scan of block sums (single block)
__global__ __launch_bounds__(512)
void scan_p2(int nb) {
    __shared__ int sh[512];
    int t = threadIdx.x;
    int v = (t < nb) ? g_bsum[t] : 0;
    sh[t] = v;
    __syncthreads();
    for (int d = 1; d < 512; d <<= 1) {
        int x = (t >= d) ? sh[t - d] : 0;
        __syncthreads();
        sh[t] += x;
        __syncthreads();
    }
    if (t < nb) g_bbase[t] = sh[t] - v;
}

// pass 3: per-block exclusive scan + base -> offsets & cursors
__global__ __launch_bounds__(256)
void scan_p3(int n, int ne) {
    __shared__ int sh[256];
    int t = threadIdx.x;
    int i = blockIdx.x * 256 + t;
    int v = (i < n) ? g_deg[i] : 0;
    sh[t] = v;
    __syncthreads();
    for (int d = 1; d < 256; d <<= 1) {
        int x = (t >= d) ? sh[t - d] : 0;
        __syncthreads();
        sh[t] += x;
        __syncthreads();
    }
    if (i < n) {
        int off = g_bbase[blockIdx.x] + sh[t] - v;
        g_off[i] = off;
        g_cursor[i] = off;
    }
    if (i == 0) g_off[n] = ne;
}

// grid-stride, 4 edges per iteration per thread
__global__ __launch_bounds__(256)
void scatter(const int* __restrict__ src, const int* __restrict__ dst, int ne) {
    int tid = blockIdx.x * blockDim.x + threadIdx.x;
    int stride = gridDim.x * blockDim.x;
    int nv = ne >> 2;
    const int4* s4 = reinterpret_cast<const int4*>(src);
    const int4* d4 = reinterpret_cast<const int4*>(dst);
    for (int i = tid; i < nv; i += stride) {
        int4 s = __ldg(&s4[i]);
        int4 d = __ldg(&d4[i]);
        int p0 = atomicAdd(&g_cursor[d.x], 1);
        int p1 = atomicAdd(&g_cursor[d.y], 1);
        int p2 = atomicAdd(&g_cursor[d.z], 1);
        int p3 = atomicAdd(&g_cursor[d.w], 1);
        g_esrc[p0] = s.x;
        g_esrc[p1] = s.y;
        g_esrc[p2] = s.z;
        g_esrc[p3] = s.w;
    }
    for (int i = (nv << 2) + tid; i < ne; i += stride) {
        int pos = atomicAdd(&g_cursor[dst[i]], 1);
        g_esrc[pos] = src[i];
    }
}

// ============================================================================
// Node kernel: input transform (lin0 or ELU of prev layer), feat = x @ W,
// el/er dots; writes packed g_fe row and rst = x + bias.
// ============================================================================
template <bool FIRST>
__global__ __launch_bounds__(128)
void node_prep(const float* __restrict__ in,
               const float* __restrict__ lin0_w, const float* __restrict__ lin0_b,
               const float* __restrict__ fc_w,
               const float* __restrict__ a_l, const float* __restrict__ a_r,
               const float* __restrict__ bias, int n_nodes) {
    __shared__ float sW[HID * HID];
    __shared__ float sW0[FIRST ? HID * HID : 1];
    __shared__ float sAl[HID], sAr[HID], sB[HID];
    __shared__ float sB0[FIRST ? HID : 1];

    int tid = threadIdx.x;
    for (int i = tid; i < HID * HID; i += blockDim.x) {
        sW[i] = fc_w[i];
        if (FIRST) sW0[i] = lin0_w[i];
    }
    for (int i = tid; i < HID; i += blockDim.x) {
        sAl[i] = a_l[i];
        sAr[i] = a_r[i];
        sB[i]  = bias[i];
        if (FIRST) sB0[i] = lin0_b[i];
    }
    __syncthreads();

    int n = blockIdx.x * blockDim.x + tid;
    if (n >= n_nodes) return;

    float x[HID];
    if (FIRST) {
        float nf[HID];
#pragma unroll
        for (int k = 0; k < HID; k++) nf[k] = in[n * HID + k];
#pragma unroll
        for (int j = 0; j < HID; j++) {
            float a = sB0[j];
#pragma unroll
            for (int k = 0; k < HID; k++) a += nf[k] * sW0[k * HID + j];
            x[j] = a;
        }
    } else {
#pragma unroll
        for (int k = 0; k < HID; k++) {
            float v = g_rst[n * HID + k];
            x[k] = v > 0.f ? v : expm1f(v);   // ELU
        }
    }

    float f[HID];
#pragma unroll
    for (int j = 0; j < HID; j++) {
        float a = 0.f;
#pragma unroll
        for (int k = 0; k < HID; k++) a += x[k] * sW[k * HID + j];
        f[j] = a;
    }

#pragma unroll
    for (int j = 0; j < HID; j++) {
        g_fe[n * FE + j] = f[j];
        g_rst[n * HID + j] = x[j] + sB[j];
    }

#pragma unroll
    for (int h = 0; h < NH; h++) {
        float l = 0.f, r = 0.f;
#pragma unroll
        for (int d = 0; d < HD; d++) {
            l += f[h * HD + d] * sAl[h * HD + d];
            r += f[h * HD + d] * sAr[h * HD + d];
        }
        g_fe[n * FE + HID + h] = l;     // el packed with feat
        g_er[n * NH + h] = r;
    }
    g_fe[n * FE + 39] = 0.f;
}

// ============================================================================
// Fused gather-aggregate: one warp per dst node, 6 edges in flight
// (3 edge slots x 2-way unroll, independent accumulator sets).
// lane = e*9 + c (e<3 edge slot, c<9 float4 chunk), h = c/3.
// Unnormalized softmax (max-subtraction dropped; e is O(1)).
// ============================================================================
__global__ __launch_bounds__(256)
void gather_agg(int n_nodes) {
    int warp = (blockIdx.x * blockDim.x + threadIdx.x) >> 5;
    if (warp >= n_nodes) return;
    int lane = threadIdx.x & 31;
    int n = warp;

    int e = lane / 9;        // 0..2 valid, 3 for lanes 27..31
    int c = lane % 9;
    int h = c / 3;
    bool chunkL = lane < 27;

    int beg = g_off[n];
    int end = g_off[n + 1];

    float er_c = (chunkL && c < 3) ? g_er[n * NH + c] : 0.f;

    float4 acc0 = make_float4(0.f, 0.f, 0.f, 0.f);
    float4 acc1 = make_float4(0.f, 0.f, 0.f, 0.f);
    float den0 = 0.f, den1 = 0.f;

    for (int i = beg; i < end; i += 6) {
        int idx0 = i + e;
        int idx1 = i + 3 + e;
        bool a0 = chunkL && (idx0 < end);
        bool a1 = chunkL && (idx1 < end);
        int s0 = a0 ? __ldg(&g_esrc[idx0]) : 0;
        int s1 = a1 ? __ldg(&g_esrc[idx1]) : 0;

        float ee0 = 0.f, ee1 = 0.f;
        if (c < 3) {
            if (a0) {
                float ev = __ldg(&g_fe[s0 * FE + HID + c]) + er_c;
                ev = ev >= 0.f ? ev : 0.2f * ev;
                ee0 = __expf(ev);
                den0 += ee0;
            }
            if (a1) {
                float ev = __ldg(&g_fe[s1 * FE + HID + c]) + er_c;
                ev = ev >= 0.f ? ev : 0.2f * ev;
                ee1 = __expf(ev);
                den1 += ee1;
            }
        }
        float w0 = __shfl_sync(FULL, ee0, e * 9 + h);
        float w1 = __shfl_sync(FULL, ee1, e * 9 + h);
        if (a0) {
            float4 f = *reinterpret_cast<const float4*>(&g_fe[s0 * FE + 4 * c]);
            acc0.x += w0 * f.x;
            acc0.y += w0 * f.y;
            acc0.z += w0 * f.z;
            acc0.w += w0 * f.w;
        }
        if (a1) {
            float4 f = *reinterpret_cast<const float4*>(&g_fe[s1 * FE + 4 * c]);
            acc1.x += w1 * f.x;
            acc1.y += w1 * f.y;
            acc1.z += w1 * f.z;
            acc1.w += w1 * f.w;
        }
    }

    float4 acc;
    acc.x = acc0.x + acc1.x;
    acc.y = acc0.y + acc1.y;
    acc.z = acc0.z + acc1.z;
    acc.w = acc0.w + acc1.w;
    float den = den0 + den1;

    // reduce the 3 edge-slot groups down to lanes 0..8
    acc.x = acc.x + __shfl_down_sync(FULL, acc.x, 9) + __shfl_down_sync(FULL, acc.x, 18);
    acc.y = acc.y + __shfl_down_sync(FULL, acc.y, 9) + __shfl_down_sync(FULL, acc.y, 18);
    acc.z = acc.z + __shfl_down_sync(FULL, acc.z, 9) + __shfl_down_sync(FULL, acc.z, 18);
    acc.w = acc.w + __shfl_down_sync(FULL, acc.w, 9) + __shfl_down_sync(FULL, acc.w, 18);
    den   = den   + __shfl_down_sync(FULL, den,   9) + __shfl_down_sync(FULL, den,   18);

    float dh = __shfl_sync(FULL, den, h);   // lanes 0..2 hold per-head totals
    if (lane < 9) {
        float inv = 1.0f / fmaxf(dh, 1e-9f);
        float4* rp = reinterpret_cast<float4*>(&g_rst[n * HID + 4 * lane]);
        float4 r = *rp;
        r.x += acc.x * inv;
        r.y += acc.y * inv;
        r.z += acc.z * inv;
        r.w += acc.w * inv;
        *rp = r;
    }
}

// ============================================================================
// Output: out = elu(rst) @ out_w + out_b
// ============================================================================
__global__ __launch_bounds__(128)
void out_proj(const float* __restrict__ out_w, const float* __restrict__ out_b,
              float* __restrict__ out, int n_nodes) {
    __shared__ float sW[HID * HID];
    __shared__ float sB[HID];
    int tid = threadIdx.x;
    for (int i = tid; i < HID * HID; i += blockDim.x) sW[i] = out_w[i];
    for (int i = tid; i < HID; i += blockDim.x) sB[i] = out_b[i];
    __syncthreads();

    int n = blockIdx.x * blockDim.x + tid;
    if (n >= n_nodes) return;

    float x[HID];
#pragma unroll
    for (int k = 0; k < HID; k++) {
        float v = g_rst[n * HID + k];
        x[k] = v > 0.f ? v : expm1f(v);
    }
#pragma unroll
    for (int j = 0; j < HID; j++) {
        float a = sB[j];
#pragma unroll
        for (int k = 0; k < HID; k++) a += x[k] * sW[k * HID + j];
        out[n * HID + j] = a;
    }
}

// ============================================================================
extern "C" void kernel_launch(void* const* d_in, const int* in_sizes, int n_in,
                              void* d_out, int out_size) {
    const float* node_features = (const float*)d_in[0];
    const int*   src           = (const int*)  d_in[1];
    const int*   dst           = (const int*)  d_in[2];
    const float* lin0_w        = (const float*)d_in[3];
    const float* lin0_b        = (const float*)d_in[4];
    const float* fc_w          = (const float*)d_in[5];
    const float* attn_l        = (const float*)d_in[6];
    const float* attn_r        = (const float*)d_in[7];
    const float* gat_bias      = (const float*)d_in[8];
    const float* out_w         = (const float*)d_in[9];
    const float* out_b         = (const float*)d_in[10];

    int n  = in_sizes[0] / HID;
    int ne = in_sizes[1];

    int nb_n = (n + 127) / 128;
    int nb_z = (n + 255) / 256;       // scan block count (256 nodes/block)
    int nb_g = (n * 32 + 255) / 256;  // one warp per node
    int nb_s = 148 * 8;               // grid-stride for hist/scatter

    // CSR build
    zero_deg<<<nb_z, 256>>>(n);
    hist<<<nb_s, 256>>>(dst, ne);
    scan_p1<<<nb_z, 256>>>(n);
    scan_p2<<<1, 512>>>(nb_z);
    scan_p3<<<nb_z, 256>>>(n, ne);
    scatter<<<nb_s, 256>>>(src, dst, ne);

    for (int l = 0; l < 3; l++) {
        if (l == 0)
            node_prep<true><<<nb_n, 128>>>(node_features, lin0_w, lin0_b,
                                           fc_w, attn_l, attn_r, gat_bias, n);
        else
            node_prep<false><<<nb_n, 128>>>(nullptr, nullptr, nullptr,
                                            fc_w + l * HID * HID,
                                            attn_l + l * HID, attn_r + l * HID,
                                            gat_bias + l * HID, n);
        gather_agg<<<nb_g, 256>>>(n);
    }
    out_proj<<<nb_n, 128>>>(out_w, out_b, (float*)d_out, n);
}

// round 6
// speedup vs baseline: 3.3222x; 1.0453x over previous
#include <cuda_runtime.h>
#include <cuda_bf16.h>
#include <cuda_fp16.h>

#define NN 100000
#define NE 3200000
#define HID 36
#define NH 3
#define HD 12
#define FEH 48           // packed fp16 row stride in halves: 36 feat + 3 el + pad = 96B
#define FULL 0xffffffffu

// ---- persistent scratch ----
__device__ __align__(128) __half g_fe[NN * FEH];  // fp16: [0..35] feat, [36..38] el
__device__ float g_er[NN * NH];
__device__ float g_rst[NN * HID];   // fp32: x + bias (+ msg added by gather)
__device__ int   g_deg[NN];
__device__ int   g_off[NN + 1];
__device__ int   g_cursor[NN];
__device__ int   g_esrc[NE];
__device__ int   g_bsum[512];
__device__ int   g_bbase[512];

// ============================================================================
// CSR construction
// ============================================================================
__global__ __launch_bounds__(256)
void zero_deg(int n) {
    int i = blockIdx.x * blockDim.x + threadIdx.x;
    if (i < n) g_deg[i] = 0;
}

__global__ __launch_bounds__(256)
void hist(const int* __restrict__ dst, int ne) {
    int tid = blockIdx.x * blockDim.x + threadIdx.x;
    int stride = gridDim.x * blockDim.x;
    int nv = ne >> 2;
    const int4* d4 = reinterpret_cast<const int4*>(dst);
    for (int i = tid; i < nv; i += stride) {
        int4 d = __ldg(&d4[i]);
        atomicAdd(&g_deg[d.x], 1);
        atomicAdd(&g_deg[d.y], 1);
        atomicAdd(&g_deg[d.z], 1);
        atomicAdd(&g_deg[d.w], 1);
    }
    for (int i = (nv << 2) + tid; i < ne; i += stride)
        atomicAdd(&g_deg[dst[i]], 1);
}

__global__ __launch_bounds__(256)
void scan_p1(int n) {
    __shared__ int sh[256];
    int t = threadIdx.x;
    int i = blockIdx.x * 256 + t;
    sh[t] = (i < n) ? g_deg[i] : 0;
    __syncthreads();
#pragma unroll
    for (int d = 128; d > 0; d >>= 1) {
        if (t < d) sh[t] += sh[t + d];
        __syncthreads();
    }
    if (t == 0) g_bsum[blockIdx.x] = sh[0];
}

__global__ __launch_bounds__(512)
void scan_p2(int nb) {
    __shared__ int sh[512];
    int t = threadIdx.x;
    int v = (t < nb) ? g_bsum[t] : 0;
    sh[t] = v;
    __syncthreads();
    for (int d = 1; d < 512; d <<= 1) {
        int x = (t >= d) ? sh[t - d] : 0;
        __syncthreads();
        sh[t] += x;
        __syncthreads();
    }
    if (t < nb) g_bbase[t] = sh[t] - v;
}

__global__ __launch_bounds__(256)
void scan_p3(int n, int ne) {
    __shared__ int sh[256];
    int t = threadIdx.x;
    int i = blockIdx.x * 256 + t;
    int v = (i < n) ? g_deg[i] : 0;
    sh[t] = v;
    __syncthreads();
    for (int d = 1; d < 256; d <<= 1) {
        int x = (t >= d) ? sh[t - d] : 0;
        __syncthreads();
        sh[t] += x;
        __syncthreads();
    }
    if (i < n) {
        int off = g_bbase[blockIdx.x] + sh[t] - v;
        g_off[i] = off;
        g_cursor[i] = off;
    }
    if (i == 0) g_off[n] = ne;
}

__global__ __launch_bounds__(256)
void scatter(const int* __restrict__ src, const int* __restrict__ dst, int ne) {
    int tid = blockIdx.x * blockDim.x + threadIdx.x;
    int stride = gridDim.x * blockDim.x;
    int nv = ne >> 2;
    const int4* s4 = reinterpret_cast<const int4*>(src);
    const int4* d4 = reinterpret_cast<const int4*>(dst);
    for (int i = tid; i < nv; i += stride) {
        int4 s = __ldg(&s4[i]);
        int4 d = __ldg(&d4[i]);
        int p0 = atomicAdd(&g_cursor[d.x], 1);
        int p1 = atomicAdd(&g_cursor[d.y], 1);
        int p2 = atomicAdd(&g_cursor[d.z], 1);
        int p3 = atomicAdd(&g_cursor[d.w], 1);
        g_esrc[p0] = s.x;
        g_esrc[p1] = s.y;
        g_esrc[p2] = s.z;
        g_esrc[p3] = s.w;
    }
    for (int i = (nv << 2) + tid; i < ne; i += stride) {
        int pos = atomicAdd(&g_cursor[dst[i]], 1);
        g_esrc[pos] = src[i];
    }
}

// ============================================================================
// Node kernel
// ============================================================================
__device__ __forceinline__ unsigned pack2(float a, float b) {
    __half2 h = __floats2half2_rn(a, b);
    return *reinterpret_cast<unsigned*>(&h);
}

template <bool FIRST>
__global__ __launch_bounds__(128)
void node_prep(const float* __restrict__ in,
               const float* __restrict__ lin0_w, const float* __restrict__ lin0_b,
               const float* __restrict__ fc_w,
               const float* __restrict__ a_l, const float* __restrict__ a_r,
               const float* __restrict__ bias, int n_nodes) {
    __shared__ float sW[HID * HID];
    __shared__ float sW0[FIRST ? HID * HID : 1];
    __shared__ float sAl[HID], sAr[HID], sB[HID];
    __shared__ float sB0[FIRST ? HID : 1];

    int tid = threadIdx.x;
    for (int i = tid; i < HID * HID; i += blockDim.x) {
        sW[i] = fc_w[i];
        if (FIRST) sW0[i] = lin0_w[i];
    }
    for (int i = tid; i < HID; i += blockDim.x) {
        sAl[i] = a_l[i];
        sAr[i] = a_r[i];
        sB[i]  = bias[i];
        if (FIRST) sB0[i] = lin0_b[i];
    }
    __syncthreads();

    int n = blockIdx.x * blockDim.x + tid;
    if (n >= n_nodes) return;

    float x[HID];
    if (FIRST) {
        float nf[HID];
#pragma unroll
        for (int k = 0; k < HID; k++) nf[k] = in[n * HID + k];
#pragma unroll
        for (int j = 0; j < HID; j++) {
            float a = sB0[j];
#pragma unroll
            for (int k = 0; k < HID; k++) a += nf[k] * sW0[k * HID + j];
            x[j] = a;
        }
    } else {
#pragma unroll
        for (int k = 0; k < HID; k++) {
            float v = g_rst[n * HID + k];
            x[k] = v > 0.f ? v : expm1f(v);   // ELU
        }
    }

    float f[HID];
#pragma unroll
    for (int j = 0; j < HID; j++) {
        float a = 0.f;
#pragma unroll
        for (int k = 0; k < HID; k++) a += x[k] * sW[k * HID + j];
        f[j] = a;
    }

#pragma unroll
    for (int j = 0; j < HID; j++)
        g_rst[n * HID + j] = x[j] + sB[j];

    float el[NH], er[NH];
#pragma unroll
    for (int h = 0; h < NH; h++) {
        float l = 0.f, r = 0.f;
#pragma unroll
        for (int d = 0; d < HD; d++) {
            l += f[h * HD + d] * sAl[h * HD + d];
            r += f[h * HD + d] * sAr[h * HD + d];
        }
        el[h] = l;
        er[h] = r;
    }
#pragma unroll
    for (int h = 0; h < NH; h++) g_er[n * NH + h] = er[h];

    // pack 36 feat + 3 el into 40 halves = 5 uint4 (80B)
    unsigned u[20];
#pragma unroll
    for (int i = 0; i < 18; i++) u[i] = pack2(f[2 * i], f[2 * i + 1]);
    u[18] = pack2(el[0], el[1]);
    u[19] = pack2(el[2], 0.f);

    uint4* dp = reinterpret_cast<uint4*>(g_fe + n * FEH);
#pragma unroll
    for (int i = 0; i < 5; i++)
        dp[i] = make_uint4(u[4 * i], u[4 * i + 1], u[4 * i + 2], u[4 * i + 3]);
}

// ============================================================================
// Fused gather-aggregate: one warp per dst node, 6 edges in flight.
// lane = e*5 + c (e<6 edge slot, c<5 uint4 chunk of the 80B packed row).
// ============================================================================
__global__ __launch_bounds__(256)
void gather_agg(int n_nodes) {
    int warp = (blockIdx.x * blockDim.x + threadIdx.x) >> 5;
    if (warp >= n_nodes) return;
    int lane = threadIdx.x & 31;
    int n = warp;

    int e = lane / 5;        // 0..5 valid; 6 for lanes 30,31
    int c = lane - e * 5;    // 0..4
    bool laneOk = lane < 30;
    bool isEl = laneOk && (c == 4);
    int srcl = e * 5 + 4;    // el-carrier lane of this edge slot

    // head of first/second float4 of this lane's 8 dims
    int ha = (c < 2) ? 0 : (c == 2 ? 1 : 2);
    int hb = (c == 0) ? 0 : (c < 3 ? 1 : 2);

    int beg = g_off[n];
    int end = g_off[n + 1];

    float er0 = g_er[n * NH + 0];
    float er1 = g_er[n * NH + 1];
    float er2 = g_er[n * NH + 2];

    float acc[8];
#pragma unroll
    for (int i = 0; i < 8; i++) acc[i] = 0.f;
    float den0 = 0.f, den1 = 0.f, den2 = 0.f;

    for (int i = beg; i < end; i += 6) {
        int idx = i + e;
        bool act = laneOk && (idx < end);
        int s = act ? __ldg(&g_esrc[idx]) : 0;

        uint4 q = make_uint4(0, 0, 0, 0);
        if (act)
            q = __ldg(reinterpret_cast<const uint4*>(g_fe + s * FEH) + c);

        float ee0 = 0.f, ee1 = 0.f, ee2 = 0.f;
        if (isEl && act) {
            float2 e01 = __half22float2(*reinterpret_cast<__half2*>(&q.z)); // halves 36,37
            float2 e23 = __half22float2(*reinterpret_cast<__half2*>(&q.w)); // halves 38,pad
            float v0 = e01.x + er0;
            float v1 = e01.y + er1;
            float v2 = e23.x + er2;
            v0 = v0 >= 0.f ? v0 : 0.2f * v0;
            v1 = v1 >= 0.f ? v1 : 0.2f * v1;
            v2 = v2 >= 0.f ? v2 : 0.2f * v2;
            ee0 = __expf(v0);
            ee1 = __expf(v1);
            ee2 = __expf(v2);
            den0 += ee0;
            den1 += ee1;
            den2 += ee2;
        }
        float w0 = __shfl_sync(FULL, ee0, srcl);
        float w1 = __shfl_sync(FULL, ee1, srcl);
        float w2 = __shfl_sync(FULL, ee2, srcl);
        float wa = (ha == 0) ? w0 : (ha == 1 ? w1 : w2);
        float wb = (hb == 0) ? w0 : (hb == 1 ? w1 : w2);
        if (c == 4) wb = 0.f;   // don't accumulate el/pad halves

        float2 f01 = __half22float2(*reinterpret_cast<__half2*>(&q.x));
        float2 f23 = __half22float2(*reinterpret_cast<__half2*>(&q.y));
        float2 f45 = __half22float2(*reinterpret_cast<__half2*>(&q.z));
        float2 f67 = __half22float2(*reinterpret_cast<__half2*>(&q.w));
        acc[0] += wa * f01.x;
        acc[1] += wa * f01.y;
        acc[2] += wa * f23.x;
        acc[3] += wa * f23.y;
        acc[4] += wb * f45.x;
        acc[5] += wb * f45.y;
        acc[6] += wb * f67.x;
        acc[7] += wb * f67.y;
    }

    // Correct 6-group (stride-5) reduction:
    // stage 1: fold groups 3,4,5 onto 0,1,2 (lanes 0-14 valid after)
    // stage 2: read BOTH +5 and +10 from the SAME post-stage-1 value.
#pragma unroll
    for (int i = 0; i < 8; i++) {
        float t = acc[i];
        t += __shfl_down_sync(FULL, t, 15);
        float a5  = __shfl_down_sync(FULL, t, 5);
        float a10 = __shfl_down_sync(FULL, t, 10);
        acc[i] = t + a5 + a10;
    }
    {
        float t = den0;
        t += __shfl_down_sync(FULL, t, 15);
        float a5  = __shfl_down_sync(FULL, t, 5);
        float a10 = __shfl_down_sync(FULL, t, 10);
        den0 = t + a5 + a10;
    }
    {
        float t = den1;
        t += __shfl_down_sync(FULL, t, 15);
        float a5  = __shfl_down_sync(FULL, t, 5);
        float a10 = __shfl_down_sync(FULL, t, 10);
        den1 = t + a5 + a10;
    }
    {
        float t = den2;
        t += __shfl_down_sync(FULL, t, 15);
        float a5  = __shfl_down_sync(FULL, t, 5);
        float a10 = __shfl_down_sync(FULL, t, 10);
        den2 = t + a5 + a10;
    }

    // totals live on lane 4 (e=0, c=4)
    float d0 = __shfl_sync(FULL, den0, 4);
    float d1 = __shfl_sync(FULL, den1, 4);
    float d2 = __shfl_sync(FULL, den2, 4);

    if (lane < 5) {
        float inv0 = 1.0f / fmaxf(d0, 1e-9f);
        float inv1 = 1.0f / fmaxf(d1, 1e-9f);
        float inv2 = 1.0f / fmaxf(d2, 1e-9f);
        float va = (ha == 0) ? inv0 : (ha == 1 ? inv1 : inv2);
        float vb = (hb == 0) ? inv0 : (hb == 1 ? inv1 : inv2);

        float* rp = g_rst + n * HID + 8 * lane;
        float4 r0 = *reinterpret_cast<float4*>(rp);
        r0.x += acc[0] * va;
        r0.y += acc[1] * va;
        r0.z += acc[2] * va;
        r0.w += acc[3] * va;
        *reinterpret_cast<float4*>(rp) = r0;
        if (lane < 4) {
            float4 r1 = *reinterpret_cast<float4*>(rp + 4);
            r1.x += acc[4] * vb;
            r1.y += acc[5] * vb;
            r1.z += acc[6] * vb;
            r1.w += acc[7] * vb;
            *reinterpret_cast<float4*>(rp + 4) = r1;
        }
    }
}

// ============================================================================
// Output: out = elu(rst) @ out_w + out_b
// ============================================================================
__global__ __launch_bounds__(128)
void out_proj(const float* __restrict__ out_w, const float* __restrict__ out_b,
              float* __restrict__ out, int n_nodes) {
    __shared__ float sW[HID * HID];
    __shared__ float sB[HID];
    int tid = threadIdx.x;
    for (int i = tid; i < HID * HID; i += blockDim.x) sW[i] = out_w[i];
    for (int i = tid; i < HID; i += blockDim.x) sB[i] = out_b[i];
    __syncthreads();

    int n = blockIdx.x * blockDim.x + tid;
    if (n >= n_nodes) return;

    float x[HID];
#pragma unroll
    for (int k = 0; k < HID; k++) {
        float v = g_rst[n * HID + k];
        x[k] = v > 0.f ? v : expm1f(v);
    }
#pragma unroll
    for (int j = 0; j < HID; j++) {
        float a = sB[j];
#pragma unroll
        for (int k = 0; k < HID; k++) a += x[k] * sW[k * HID + j];
        out[n * HID + j] = a;
    }
}

// ============================================================================
extern "C" void kernel_launch(void* const* d_in, const int* in_sizes, int n_in,
                              void* d_out, int out_size) {
    const float* node_features = (const float*)d_in[0];
    const int*   src           = (const int*)  d_in[1];
    const int*   dst           = (const int*)  d_in[2];
    const float* lin0_w        = (const float*)d_in[3];
    const float* lin0_b        = (const float*)d_in[4];
    const float* fc_w          = (const float*)d_in[5];
    const float* attn_l        = (const float*)d_in[6];
    const float* attn_r        = (const float*)d_in[7];
    const float* gat_bias      = (const float*)d_in[8];
    const float* out_w         = (const float*)d_in[9];
    const float* out_b         = (const float*)d_in[10];

    int n  = in_sizes[0] / HID;
    int ne = in_sizes[1];

    int nb_n = (n + 127) / 128;
    int nb_z = (n + 255) / 256;
    int nb_g = (n * 32 + 255) / 256;
    int nb_s = 148 * 8;

    zero_deg<<<nb_z, 256>>>(n);
    hist<<<nb_s, 256>>>(dst, ne);
    scan_p1<<<nb_z, 256>>>(n);
    scan_p2<<<1, 512>>>(nb_z);
    scan_p3<<<nb_z, 256>>>(n, ne);
    scatter<<<nb_s, 256>>>(src, dst, ne);

    for (int l = 0; l < 3; l++) {
        if (l == 0)
            node_prep<true><<<nb_n, 128>>>(node_features, lin0_w, lin0_b,
                                           fc_w, attn_l, attn_r, gat_bias, n);
        else
            node_prep<false><<<nb_n, 128>>>(nullptr, nullptr, nullptr,
                                            fc_w + l * HID * HID,
                                            attn_l + l * HID, attn_r + l * HID,
                                            gat_bias + l * HID, n);
        gather_agg<<<nb_g, 256>>>(n);
    }
    out_proj<<<nb_n, 128>>>(out_w, out_b, (float*)d_out, n);
}